// round 8
// baseline (speedup 1.0000x reference)
#include <cuda_runtime.h>

// Fully fused quanvolution + linear + log_softmax.
// Closed trig forms (rz gates drop; circuit factors into small components):
//   Z0 = cos(t0)cos(t9)cos d0 - sin(t9)sin d0     Z5 = cos(d5 + t5)
//   Z1 = cos(d1 + t1)                             Z6 = cos d6
//   Z2 = cos d2                                   Z7 = cos d6 cos d7
//   Z3 = cos(t12) cos d2 cos d3                   Z8 = cos(t8) cos d7 cos d8
//   Z4 = cos(t4)cos(t13)cos d3 cos d4 - sin(t13)sin d4
// Latency-bound; grid=512 x 192 threads (small barrier scope wins over fewer
// blocks — 4-img/block measured slower). DRAM image burst issued FIRST, then
// L2-resident W prefetch, so the barrier's long pole heads the LSU queue.

#define IMG_W 28
#define IMG_PIX 784
#define N_PATCH 169
#define FEAT 1521
#define NTHREADS 192

__global__ void __launch_bounds__(NTHREADS, 3) quanv_fused_kernel(
    const float* __restrict__ x,     // [bsz, 28, 28]
    const float* __restrict__ qp,    // [16]
    const float* __restrict__ W,     // [2, 1521]
    const float* __restrict__ bias,  // [2]
    float* __restrict__ out)         // [bsz, 2]
{
    __shared__ __align__(16) float sx[IMG_PIX];  // staged image
    __shared__ float g[10];                      // gate trig constants
    __shared__ float warp0[6], warp1[6];

    const int t   = threadIdx.x;
    const int img = blockIdx.x;

    // ---- Cold-DRAM image burst FIRST: 784 floats = 196 float4 loads ----
    {
        const float4* src = (const float4*)(x + img * IMG_PIX);
        float4* dst = (float4*)sx;
        dst[t] = __ldg(src + t);
        if (t < 196 - NTHREADS) dst[NTHREADS + t] = __ldg(src + NTHREADS + t);
    }

    // ---- L2-resident prefetches, overlapped with the DRAM latency ----
    float w0r[9], w1r[9];
    if (t < N_PATCH) {
        const float* w0 = W + t * 9;
        const float* w1 = W + FEAT + t * 9;
        #pragma unroll
        for (int k = 0; k < 9; k++) { w0r[k] = __ldg(w0 + k); w1r[k] = __ldg(w1 + k); }
    }
    float b0 = 0.f, b1 = 0.f;
    if (t == 0) { b0 = __ldg(bias + 0); b1 = __ldg(bias + 1); }

    if (t == 0) {
        const float th0  = qp[0],  th1  = qp[1];
        const float th4  = qp[4],  th5  = qp[5];
        const float th8  = qp[8],  th9  = qp[9];
        const float th12 = qp[12], th13 = qp[13];
        float s1g, c1g, s5g, c5g;
        __sincosf(th1, &s1g, &c1g);
        __sincosf(th5, &s5g, &c5g);
        g[0] = __cosf(th0) * __cosf(th9);    // Z0 cos-term
        g[1] = __sinf(th9);                  // Z0 sin-term
        g[2] = c1g;  g[3] = s1g;             // cos/sin t1
        g[4] = __cosf(th12);                 // Z3 factor
        g[5] = __cosf(th4) * __cosf(th13);   // Z4 cos-term
        g[6] = __sinf(th13);                 // Z4 sin-term
        g[7] = c5g;  g[8] = s5g;             // cos/sin t5
        g[9] = __cosf(th8);                  // Z8 factor
    }
    __syncthreads();

    float s0 = 0.f, s1 = 0.f;

    if (t < N_PATCH) {
        const int pi = t / 13;
        const int pj = t - pi * 13;
        const float* xb = sx + (2 * pi) * IMG_W + 2 * pj;

        const float d0 = xb[0],              d1 = xb[1],              d2 = xb[2];
        const float d3 = xb[IMG_W],          d4 = xb[IMG_W + 1],      d5 = xb[IMG_W + 2];
        const float d6 = xb[2 * IMG_W],      d7 = xb[2 * IMG_W + 1],  d8 = xb[2 * IMG_W + 2];

        float sd0, cd0, sd1, cd1, sd4, cd4, sd5, cd5;
        __sincosf(d0, &sd0, &cd0);
        __sincosf(d1, &sd1, &cd1);
        __sincosf(d4, &sd4, &cd4);
        __sincosf(d5, &sd5, &cd5);
        const float cd2 = __cosf(d2);
        const float cd3 = __cosf(d3);
        const float cd6 = __cosf(d6);
        const float cd7 = __cosf(d7);
        const float cd8 = __cosf(d8);

        const float z0 = g[0] * cd0 - g[1] * sd0;
        const float z1 = g[2] * cd1 - g[3] * sd1;      // cos(d1 + t1)
        const float z3 = g[4] * cd2 * cd3;
        const float z4 = g[5] * cd3 * cd4 - g[6] * sd4;
        const float z5 = g[7] * cd5 - g[8] * sd5;      // cos(d5 + t5)
        const float z7 = cd6 * cd7;
        const float z8 = g[9] * cd7 * cd8;

        s0 = z0 * w0r[0];                  s1 = z0 * w1r[0];
        s0 = fmaf(z1,  w0r[1], s0);        s1 = fmaf(z1,  w1r[1], s1);
        s0 = fmaf(cd2, w0r[2], s0);        s1 = fmaf(cd2, w1r[2], s1);
        s0 = fmaf(z3,  w0r[3], s0);        s1 = fmaf(z3,  w1r[3], s1);
        s0 = fmaf(z4,  w0r[4], s0);        s1 = fmaf(z4,  w1r[4], s1);
        s0 = fmaf(z5,  w0r[5], s0);        s1 = fmaf(z5,  w1r[5], s1);
        s0 = fmaf(cd6, w0r[6], s0);        s1 = fmaf(cd6, w1r[6], s1);
        s0 = fmaf(z7,  w0r[7], s0);        s1 = fmaf(z7,  w1r[7], s1);
        s0 = fmaf(z8,  w0r[8], s0);        s1 = fmaf(z8,  w1r[8], s1);
    }

    // warp-level reduction of (s0, s1)
    #pragma unroll
    for (int off = 16; off > 0; off >>= 1) {
        s0 += __shfl_down_sync(0xffffffffu, s0, off);
        s1 += __shfl_down_sync(0xffffffffu, s1, off);
    }
    const int wid = t >> 5;
    if ((t & 31) == 0) { warp0[wid] = s0; warp1[wid] = s1; }
    __syncthreads();

    if (t == 0) {
        float l0 = b0, l1 = b1;
        #pragma unroll
        for (int i = 0; i < 6; i++) { l0 += warp0[i]; l1 += warp1[i]; }
        const float m   = fmaxf(l0, l1);
        const float lse = m + __logf(__expf(l0 - m) + __expf(l1 - m));
        float2 res = make_float2(l0 - lse, l1 - lse);
        *(float2*)(out + img * 2) = res;
    }
}

extern "C" void kernel_launch(void* const* d_in, const int* in_sizes, int n_in,
                              void* d_out, int out_size) {
    const float* x  = (const float*)d_in[0];
    const float* qp = (const float*)d_in[1];
    const float* W  = (const float*)d_in[2];
    const float* b  = (const float*)d_in[3];
    float* out = (float*)d_out;

    const int bsz = in_sizes[0] / IMG_PIX;   // 512
    quanv_fused_kernel<<<bsz, NTHREADS>>>(x, qp, W, b, out);
}

// round 9
// speedup vs baseline: 1.1224x; 1.1224x over previous
#include <cuda_runtime.h>

// Fully fused quanvolution + linear + log_softmax.
// Closed trig forms (rz gates drop; circuit factors into small components):
//   Z0 = cos(t0)cos(t9)cos d0 - sin(t9)sin d0     Z5 = cos(d5 + t5)
//   Z1 = cos(d1 + t1)                             Z6 = cos d6
//   Z2 = cos d2                                   Z7 = cos d6 cos d7
//   Z3 = cos(t12) cos d2 cos d3                   Z8 = cos(t8) cos d7 cos d8
//   Z4 = cos(t4)cos(t13)cos d3 cos d4 - sin(t13)sin d4
// Latency-bound; grid=512 x 192. Gate constants are image-independent and are
// computed REDUNDANTLY per patch-thread (overlapped with the DRAM image burst)
// so the staging barrier no longer waits on a serial thread-0 trig chain.

#define IMG_W 28
#define IMG_PIX 784
#define N_PATCH 169
#define FEAT 1521
#define NTHREADS 192

__global__ void __launch_bounds__(NTHREADS, 3) quanv_fused_kernel(
    const float* __restrict__ x,     // [bsz, 28, 28]
    const float* __restrict__ qp,    // [16]
    const float* __restrict__ W,     // [2, 1521]
    const float* __restrict__ bias,  // [2]
    float* __restrict__ out)         // [bsz, 2]
{
    __shared__ __align__(16) float sx[IMG_PIX];  // staged image
    __shared__ float warp0[6], warp1[6];

    const int t   = threadIdx.x;
    const int img = blockIdx.x;

    // ---- Cold-DRAM image burst FIRST: 784 floats = 196 float4 loads ----
    {
        const float4* src = (const float4*)(x + img * IMG_PIX);
        float4* dst = (float4*)sx;
        dst[t] = __ldg(src + t);
        if (t < 196 - NTHREADS) dst[NTHREADS + t] = __ldg(src + NTHREADS + t);
    }

    // ---- Independent, L2/const-cached prefetches under the DRAM shadow ----
    float w0r[9], w1r[9];
    float g0, g1, gc1, gs1, g4, g5, g6, gc5, gs5, g9;
    if (t < N_PATCH) {
        const float* w0 = W + t * 9;
        const float* w1 = W + FEAT + t * 9;
        #pragma unroll
        for (int k = 0; k < 9; k++) { w0r[k] = __ldg(w0 + k); w1r[k] = __ldg(w1 + k); }

        const float th0  = __ldg(qp + 0),  th1  = __ldg(qp + 1);
        const float th4  = __ldg(qp + 4),  th5  = __ldg(qp + 5);
        const float th8  = __ldg(qp + 8),  th9  = __ldg(qp + 9);
        const float th12 = __ldg(qp + 12), th13 = __ldg(qp + 13);
        __sincosf(th1, &gs1, &gc1);            // cos/sin t1
        __sincosf(th5, &gs5, &gc5);            // cos/sin t5
        g0 = __cosf(th0) * __cosf(th9);        // Z0 cos-term
        g1 = __sinf(th9);                      // Z0 sin-term
        g4 = __cosf(th12);                     // Z3 factor
        g5 = __cosf(th4) * __cosf(th13);       // Z4 cos-term
        g6 = __sinf(th13);                     // Z4 sin-term
        g9 = __cosf(th8);                      // Z8 factor
    }
    float b0 = 0.f, b1 = 0.f;
    if (t == 0) { b0 = __ldg(bias + 0); b1 = __ldg(bias + 1); }

    __syncthreads();   // waits only on staging stores now

    float s0 = 0.f, s1 = 0.f;

    if (t < N_PATCH) {
        const int pi = t / 13;
        const int pj = t - pi * 13;
        const float* xb = sx + (2 * pi) * IMG_W + 2 * pj;

        const float d0 = xb[0],              d1 = xb[1],              d2 = xb[2];
        const float d3 = xb[IMG_W],          d4 = xb[IMG_W + 1],      d5 = xb[IMG_W + 2];
        const float d6 = xb[2 * IMG_W],      d7 = xb[2 * IMG_W + 1],  d8 = xb[2 * IMG_W + 2];

        float sd0, cd0, sd1, cd1, sd4, cd4, sd5, cd5;
        __sincosf(d0, &sd0, &cd0);
        __sincosf(d1, &sd1, &cd1);
        __sincosf(d4, &sd4, &cd4);
        __sincosf(d5, &sd5, &cd5);
        const float cd2 = __cosf(d2);
        const float cd3 = __cosf(d3);
        const float cd6 = __cosf(d6);
        const float cd7 = __cosf(d7);
        const float cd8 = __cosf(d8);

        const float z0 = g0  * cd0 - g1  * sd0;
        const float z1 = gc1 * cd1 - gs1 * sd1;        // cos(d1 + t1)
        const float z3 = g4  * cd2 * cd3;
        const float z4 = g5  * cd3 * cd4 - g6 * sd4;
        const float z5 = gc5 * cd5 - gs5 * sd5;        // cos(d5 + t5)
        const float z7 = cd6 * cd7;
        const float z8 = g9  * cd7 * cd8;

        s0 = z0 * w0r[0];                  s1 = z0 * w1r[0];
        s0 = fmaf(z1,  w0r[1], s0);        s1 = fmaf(z1,  w1r[1], s1);
        s0 = fmaf(cd2, w0r[2], s0);        s1 = fmaf(cd2, w1r[2], s1);
        s0 = fmaf(z3,  w0r[3], s0);        s1 = fmaf(z3,  w1r[3], s1);
        s0 = fmaf(z4,  w0r[4], s0);        s1 = fmaf(z4,  w1r[4], s1);
        s0 = fmaf(z5,  w0r[5], s0);        s1 = fmaf(z5,  w1r[5], s1);
        s0 = fmaf(cd6, w0r[6], s0);        s1 = fmaf(cd6, w1r[6], s1);
        s0 = fmaf(z7,  w0r[7], s0);        s1 = fmaf(z7,  w1r[7], s1);
        s0 = fmaf(z8,  w0r[8], s0);        s1 = fmaf(z8,  w1r[8], s1);
    }

    // warp-level reduction of (s0, s1)
    #pragma unroll
    for (int off = 16; off > 0; off >>= 1) {
        s0 += __shfl_down_sync(0xffffffffu, s0, off);
        s1 += __shfl_down_sync(0xffffffffu, s1, off);
    }
    const int wid = t >> 5;
    if ((t & 31) == 0) { warp0[wid] = s0; warp1[wid] = s1; }
    __syncthreads();

    if (t == 0) {
        float l0 = b0, l1 = b1;
        #pragma unroll
        for (int i = 0; i < 6; i++) { l0 += warp0[i]; l1 += warp1[i]; }
        const float m   = fmaxf(l0, l1);
        const float lse = m + __logf(__expf(l0 - m) + __expf(l1 - m));
        float2 res = make_float2(l0 - lse, l1 - lse);
        *(float2*)(out + img * 2) = res;
    }
}

extern "C" void kernel_launch(void* const* d_in, const int* in_sizes, int n_in,
                              void* d_out, int out_size) {
    const float* x  = (const float*)d_in[0];
    const float* qp = (const float*)d_in[1];
    const float* W  = (const float*)d_in[2];
    const float* b  = (const float*)d_in[3];
    float* out = (float*)d_out;

    const int bsz = in_sizes[0] / IMG_PIX;   // 512
    quanv_fused_kernel<<<bsz, NTHREADS>>>(x, qp, W, b, out);
}